// round 10
// baseline (speedup 1.0000x reference)
#include <cuda_runtime.h>
#include <cstdint>

#define Nn   2048
#define Ee   65536
#define INC  128
#define HIDc 32
#define LATc 16

typedef unsigned long long ull;

// ---------------- scratch (static zero; self-cleaning each run) ----------------
__device__ float g_deg [Nn];                       // edge count only; reset in k_zhij
__device__ __align__(16) float g_xw   [Nn*HIDc];
__device__ __align__(16) float g_agg1 [Nn*HIDc];  // reset in k_h1hw
__device__ __align__(16) float g_hwmu [Nn*LATc];
__device__ __align__(16) float g_hwlv [Nn*LATc];
__device__ __align__(16) float g_aggmu[Nn*LATc];  // reset in k_zhij
__device__ __align__(16) float g_agglv[Nn*LATc];  // reset in k_zhij
__device__ __align__(16) float g_hi   [Nn*LATc];
__device__ __align__(16) float g_hjT  [LATc*Nn];  // transposed: [l][i]

// ---------------- helpers ----------------
__device__ __forceinline__ int eidx(const void* p, int pos, int is64) {
    if (is64) return (int)((const long long*)p)[pos];
    return ((const int*)p)[pos];
}
// per-block dtype detect: ids < 2048 => int64 storage has zero high words
__device__ __forceinline__ int detect64(const void* p_) {
    const ull* p = (const ull*)p_;
    ull orv = 0;
#pragma unroll
    for (int k = 0; k < 64; k++) orv |= p[k];
    return ((orv >> 32) == 0ull) ? 1 : 0;
}
__device__ __forceinline__ void red4(float* addr, float4 v) {
    asm volatile("red.global.add.v4.f32 [%0], {%1, %2, %3, %4};"
                 :: "l"(__cvta_generic_to_global(addr)),
                    "f"(v.x), "f"(v.y), "f"(v.z), "f"(v.w) : "memory");
}

// ---------------- kernels ----------------

// deg atomics (critical chain start)
__global__ void k_deg(const void* __restrict__ ei) {
    __shared__ int s64;
    if (threadIdx.x == 0) s64 = detect64(ei);
    __syncthreads();
    int e = blockIdx.x * 256 + threadIdx.x;          // 65536 threads
    atomicAdd(&g_deg[eidx(ei, Ee + e, s64)], 1.0f);
}

// side stream: xw = x @ W1 (2048x128 @ 128x32), warp per row
__global__ void k_xw(const float* __restrict__ x, const float* __restrict__ W1) {
    __shared__ float xs[8][INC];
    int tid = threadIdx.y * 32 + threadIdx.x;
    for (int t = tid; t < 8 * INC; t += 256) {
        int r = t / INC, k = t % INC;
        xs[r][k] = x[(blockIdx.x * 8 + r) * INC + k];
    }
    __syncthreads();
    int row = blockIdx.x * 8 + threadIdx.y;
    int c   = threadIdx.x;
    float s = 0.f;
#pragma unroll 8
    for (int k = 0; k < INC; k++) s = fmaf(xs[threadIdx.y][k], W1[k * HIDc + c], s);
    g_xw[row * HIDc + c] = s;
}

// side stream: zero adj_true
__global__ void k_zero(float4* __restrict__ p) {
    int t = blockIdx.x * 256 + threadIdx.x;          // 262144 threads
#pragma unroll
    for (int k = 0; k < 4; k++)
        p[t + k * 262144] = make_float4(0.f, 0.f, 0.f, 0.f);
}

// side stream: scatter multiplicity into adj_true
__global__ void k_true(const void* __restrict__ eit, float* __restrict__ adj) {
    __shared__ int s64;
    if (threadIdx.x == 0) s64 = detect64(eit);
    __syncthreads();
    int e = blockIdx.x * 256 + threadIdx.x;
    atomicAdd(&adj[eidx(eit, e, s64) * Nn + eidx(eit, Ee + e, s64)], 1.0f);
}

// edge aggregation layer 1: 4 edges/thread (ILP), deg in smem, fused rsqrt
__global__ void k_eagg1(const void* __restrict__ ei) {
    __shared__ int   s64;
    __shared__ float sdeg[Nn];
    int tx = threadIdx.x;
    if (tx == 0) s64 = detect64(ei);
    for (int i = tx; i < Nn; i += 256) sdeg[i] = g_deg[i];
    __syncthreads();
    int is64 = s64;
    int t = blockIdx.x * 256 + tx;                   // 65536 threads
    int c = t & 3, e0 = t >> 2;                      // e0 in 0..16383
    int s[4], d[4];
#pragma unroll
    for (int k = 0; k < 4; k++) {
        int e = e0 + k * 16384;
        s[k] = eidx(ei, e, is64);
        d[k] = eidx(ei, Ee + e, is64);
    }
    float nw[4];
#pragma unroll
    for (int k = 0; k < 4; k++)
        nw[k] = rsqrtf((sdeg[s[k]] + 1.0f) * (sdeg[d[k]] + 1.0f));
    const float4* xw4 = (const float4*)g_xw;
    float4 a[4], b[4];
#pragma unroll
    for (int k = 0; k < 4; k++) {
        a[k] = xw4[s[k] * 8 + c];
        b[k] = xw4[s[k] * 8 + c + 4];
    }
#pragma unroll
    for (int k = 0; k < 4; k++) {
        float w = nw[k];
        a[k].x *= w; a[k].y *= w; a[k].z *= w; a[k].w *= w;
        b[k].x *= w; b[k].y *= w; b[k].z *= w; b[k].w *= w;
        red4(&g_agg1[d[k] * HIDc + c * 4], a[k]);
        red4(&g_agg1[d[k] * HIDc + (c + 4) * 4], b[k]);
    }
}

// h1 = relu(agg + selfloop + b1) fused with hw = h1 @ {W_mu, W_lv}; reset agg1
__global__ void k_h1hw(const float* __restrict__ b1,
                       const float* __restrict__ Wmu, const float* __restrict__ Wlv) {
    int row  = blockIdx.x * 8 + (threadIdx.x >> 5);
    int lane = threadIdx.x & 31;
    float di = rsqrtf(g_deg[row] + 1.0f);
    int idx = row * HIDc + lane;
    float h = fmaxf(g_agg1[idx] + di * di * g_xw[idx] + b1[lane], 0.f);
    g_agg1[idx] = 0.f;                               // reset for next replay
    const float* W = (lane < 16) ? Wmu : Wlv;
    int l = lane & 15;
    float s = 0.f;
#pragma unroll
    for (int k = 0; k < HIDc; k++) {
        float hk = __shfl_sync(0xffffffffu, h, k);
        s = fmaf(hk, W[k * LATc + l], s);
    }
    if (lane < 16) g_hwmu[row * LATc + l] = s;
    else           g_hwlv[row * LATc + l] = s;
}

// edge aggregation layer 2: 4 edges/thread, deg in smem, fused rsqrt
__global__ void k_eagg2(const void* __restrict__ ei) {
    __shared__ int   s64;
    __shared__ float sdeg[Nn];
    int tx = threadIdx.x;
    if (tx == 0) s64 = detect64(ei);
    for (int i = tx; i < Nn; i += 256) sdeg[i] = g_deg[i];
    __syncthreads();
    int is64 = s64;
    int t = blockIdx.x * 256 + tx;
    int c = t & 3, e0 = t >> 2;
    int s[4], d[4];
#pragma unroll
    for (int k = 0; k < 4; k++) {
        int e = e0 + k * 16384;
        s[k] = eidx(ei, e, is64);
        d[k] = eidx(ei, Ee + e, is64);
    }
    float nw[4];
#pragma unroll
    for (int k = 0; k < 4; k++)
        nw[k] = rsqrtf((sdeg[s[k]] + 1.0f) * (sdeg[d[k]] + 1.0f));
    float4 a[4], b[4];
#pragma unroll
    for (int k = 0; k < 4; k++) {
        a[k] = ((const float4*)g_hwmu)[s[k] * 4 + c];
        b[k] = ((const float4*)g_hwlv)[s[k] * 4 + c];
    }
#pragma unroll
    for (int k = 0; k < 4; k++) {
        float w = nw[k];
        a[k].x *= w; a[k].y *= w; a[k].z *= w; a[k].w *= w;
        b[k].x *= w; b[k].y *= w; b[k].z *= w; b[k].w *= w;
        red4(&g_aggmu[d[k] * LATc + c * 4], a[k]);
        red4(&g_agglv[d[k] * LATc + c * 4], b[k]);
    }
}

// mu/logvar out, z (regs), hi/hjT via shfl-16 matvec; reset aggmu/agglv/deg
__global__ void k_zhij(const float* __restrict__ bmu, const float* __restrict__ blv,
                       const float* __restrict__ eps,
                       const float* __restrict__ dW1, const float* __restrict__ db1,
                       float* __restrict__ out_mu, float* __restrict__ out_lv) {
    int t = blockIdx.x * 256 + threadIdx.x;          // Nn*LATc threads
    int i = t >> 4, l = t & 15;
    float di = rsqrtf(g_deg[i] + 1.0f);
    float d2 = di * di;
    float mu = g_aggmu[t] + d2 * g_hwmu[t] + bmu[l];
    float lv = g_agglv[t] + d2 * g_hwlv[t] + blv[l];
    g_aggmu[t] = 0.f; g_agglv[t] = 0.f;              // reset for next replay
    if (l == 0) g_deg[i] = 0.f;                      // last consumer resets deg
    out_mu[t] = mu;
    out_lv[t] = lv;
    float z = fmaf(eps[t], __expf(0.5f * lv), mu);
    float si = db1[l], sj = 0.f;
#pragma unroll
    for (int k = 0; k < LATc; k++) {
        float zk = __shfl_sync(0xffffffffu, z, k, 16);
        si = fmaf(zk, dW1[k * LATc + l], si);
        sj = fmaf(zk, dW1[(LATc + k) * LATc + l], sj);
    }
    g_hi[t] = si;
    g_hjT[l * Nn + i] = sj;                          // transposed for decoder
}

// decoder: scalar math, 2 j per thread, tile 8 rows x 512 cols
__global__ void __launch_bounds__(256) k_dec(const float* __restrict__ dW2,
                                             const float* __restrict__ db2,
                                             float* __restrict__ adj) {
    __shared__ float his[8][16];
    int tx = threadIdx.x;
    int j0 = blockIdx.x * 512;
    int i0 = blockIdx.y * 8;

    if (tx < 128) his[tx >> 4][tx & 15] = g_hi[(i0 + (tx >> 4)) * LATc + (tx & 15)];

    float w2r[LATc];
    float2 hj[LATc];
#pragma unroll
    for (int l = 0; l < LATc; l++) {
        w2r[l] = dW2[l];
        hj[l] = *(const float2*)&g_hjT[l * Nn + j0 + 2 * tx];
    }
    float b2 = db2[0];
    __syncthreads();

    size_t obase = (size_t)i0 * Nn + j0 + 2 * tx;
#pragma unroll
    for (int r = 0; r < 8; r++) {
        float ax = b2, ay = b2;
#pragma unroll
        for (int l = 0; l < LATc; l++) {
            float h = his[r][l];
            ax = fmaf(fmaxf(h + hj[l].x, 0.f), w2r[l], ax);
            ay = fmaf(fmaxf(h + hj[l].y, 0.f), w2r[l], ay);
        }
        float2 o;
        o.x = __fdividef(1.f, 1.f + __expf(-ax));
        o.y = __fdividef(1.f, 1.f + __expf(-ay));
        *(float2*)&adj[obase + (size_t)r * Nn] = o;
    }
}

// ---------------- launcher ----------------
extern "C" void kernel_launch(void* const* d_in, const int* in_sizes, int n_in,
                              void* d_out, int out_size) {
    const float* x    = (const float*)d_in[0];
    const float* eps  = (const float*)d_in[1];
    const float* W1   = (const float*)d_in[2];
    const float* b1   = (const float*)d_in[3];
    const float* Wmu  = (const float*)d_in[4];
    const float* bmu  = (const float*)d_in[5];
    const float* Wlv  = (const float*)d_in[6];
    const float* blv  = (const float*)d_in[7];
    const float* dW1  = (const float*)d_in[8];
    const float* db1  = (const float*)d_in[9];
    const float* dW2  = (const float*)d_in[10];
    const float* db2  = (const float*)d_in[11];
    const void*  ei   = d_in[12];
    const void*  eit  = d_in[13];

    float* out      = (float*)d_out;
    float* adj_pred = out;
    float* adj_true = out + (size_t)Nn * Nn;
    float* out_mu   = out + 2 * (size_t)Nn * Nn;
    float* out_lv   = out_mu + Nn * LATc;

    // side stream + fork/join events (capture-legal). Never destroyed: destroying
    // a stream/event that participated in an open capture would invalidate it;
    // kernel_launch runs only a handful of times so the host-side leak is nil.
    cudaStream_t s2 = 0;
    cudaEvent_t eF = 0, eX = 0, eJ = 0;
    bool multi =
        cudaStreamCreateWithFlags(&s2, cudaStreamNonBlocking) == cudaSuccess &&
        cudaEventCreateWithFlags(&eF, cudaEventDisableTiming) == cudaSuccess &&
        cudaEventCreateWithFlags(&eX, cudaEventDisableTiming) == cudaSuccess &&
        cudaEventCreateWithFlags(&eJ, cudaEventDisableTiming) == cudaSuccess;

    if (multi) {
        cudaEventRecord(eF, 0);                       // fork point
        cudaStreamWaitEvent(s2, eF, 0);
        // side chain: xw (gates eagg1) then adj_true zero + scatter
        k_xw  <<<Nn / 8, dim3(32, 8), 0, s2>>>(x, W1);
        cudaEventRecord(eX, s2);
        k_zero<<<1024, 256, 0, s2>>>((float4*)adj_true);
        k_true<<<Ee / 256, 256, 0, s2>>>(eit, adj_true);
        cudaEventRecord(eJ, s2);                      // join point
        // main chain
        k_deg  <<<Ee / 256, 256>>>(ei);
        cudaStreamWaitEvent(0, eX, 0);                // need xw before eagg1
        k_eagg1<<<256, 256>>>(ei);
        k_h1hw <<<256, 256>>>(b1, Wmu, Wlv);
        k_eagg2<<<256, 256>>>(ei);
        k_zhij <<<128, 256>>>(bmu, blv, eps, dW1, db1, out_mu, out_lv);
        cudaStreamWaitEvent(0, eJ, 0);                // join side chain
        k_dec  <<<dim3(4, 256), 256>>>(dW2, db2, adj_pred);
    } else {
        // fallback: fully serialized on the captured stream
        k_deg  <<<Ee / 256, 256>>>(ei);
        k_xw   <<<Nn / 8, dim3(32, 8)>>>(x, W1);
        k_zero <<<1024, 256>>>((float4*)adj_true);
        k_true <<<Ee / 256, 256>>>(eit, adj_true);
        k_eagg1<<<256, 256>>>(ei);
        k_h1hw <<<256, 256>>>(b1, Wmu, Wlv);
        k_eagg2<<<256, 256>>>(ei);
        k_zhij <<<128, 256>>>(bmu, blv, eps, dW1, db1, out_mu, out_lv);
        k_dec  <<<dim3(4, 256), 256>>>(dW2, db2, adj_pred);
    }
}

// round 11
// speedup vs baseline: 1.0789x; 1.0789x over previous
#include <cuda_runtime.h>
#include <cstdint>

#define Nn   2048
#define Ee   65536
#define INC  128
#define HIDc 32
#define LATc 16

typedef unsigned long long ull;

// ---------------- scratch (static zero; self-cleaning each run) ----------------
__device__ float g_deg [Nn];                       // edge count only; reset in k_zhij
__device__ __align__(16) float g_xw   [Nn*HIDc];
__device__ __align__(16) float g_agg1 [Nn*HIDc];  // reset in k_h1hw
__device__ __align__(16) float g_hwmu [Nn*LATc];
__device__ __align__(16) float g_hwlv [Nn*LATc];
__device__ __align__(16) float g_aggmu[Nn*LATc];  // reset in k_zhij
__device__ __align__(16) float g_agglv[Nn*LATc];  // reset in k_zhij
__device__ __align__(16) float g_hi   [Nn*LATc];
__device__ __align__(16) float g_hjT  [LATc*Nn];  // transposed: [l][i]

// ---------------- helpers ----------------
__device__ __forceinline__ int eidx(const void* p, int pos, int is64) {
    if (is64) return (int)((const long long*)p)[pos];
    return ((const int*)p)[pos];
}
// per-block dtype detect: ids < 2048 => int64 storage has zero high words
__device__ __forceinline__ int detect64(const void* p_) {
    const ull* p = (const ull*)p_;
    ull orv = 0;
#pragma unroll
    for (int k = 0; k < 64; k++) orv |= p[k];
    return ((orv >> 32) == 0ull) ? 1 : 0;
}
__device__ __forceinline__ void red4(float* addr, float4 v) {
    asm volatile("red.global.add.v4.f32 [%0], {%1, %2, %3, %4};"
                 :: "l"(__cvta_generic_to_global(addr)),
                    "f"(v.x), "f"(v.y), "f"(v.z), "f"(v.w) : "memory");
}

// ---------------- kernels ----------------

// L1: deg atomics | xw = x @ W1 (8 rows/block) | zero adj_true  (all independent)
__global__ void k_pre(const void* __restrict__ ei,
                      const float* __restrict__ x, const float* __restrict__ W1,
                      float4* __restrict__ adjt4) {
    __shared__ float xs[8][INC];
    __shared__ int   s64;
    int tid = threadIdx.x;                            // 256 threads, 256 blocks
    int t   = blockIdx.x * 256 + tid;                 // 0..65535
    if (tid == 0) s64 = detect64(ei);

    // zero adj_true: 16 float4 per thread (coalesced, full 16.8MB)
#pragma unroll
    for (int k = 0; k < 16; k++)
        adjt4[t + k * 65536] = make_float4(0.f, 0.f, 0.f, 0.f);

    // fill x tile for this block's 8 GEMM rows
    for (int u = tid; u < 8 * INC; u += 256) {
        int r = u / INC, k = u % INC;
        xs[r][k] = x[(blockIdx.x * 8 + r) * INC + k];
    }
    __syncthreads();

    // one degree atomic per thread
    atomicAdd(&g_deg[eidx(ei, Ee + t, s64)], 1.0f);

    // warp-per-row GEMM: row = 8*block + warp, c = lane
    int row = blockIdx.x * 8 + (tid >> 5);
    int c   = tid & 31;
    float s = 0.f;
#pragma unroll 8
    for (int k = 0; k < INC; k++) s = fmaf(xs[tid >> 5][k], W1[k * HIDc + c], s);
    g_xw[row * HIDc + c] = s;
}

// L2: eagg1 (4 edges/thread, smem deg, fused rsqrt) | adj_true scatter
__global__ void k_eagg1true(const void* __restrict__ ei,
                            const void* __restrict__ eit, float* __restrict__ adjt) {
    __shared__ int   s64, s64t;
    __shared__ float sdeg[Nn];
    int tx = threadIdx.x;
    if (tx == 0)      s64  = detect64(ei);
    else if (tx == 32) s64t = detect64(eit);
    for (int i = tx; i < Nn; i += 256) sdeg[i] = g_deg[i];
    __syncthreads();
    int is64 = s64;
    int t = blockIdx.x * 256 + tx;                    // 65536 threads

    // adj_true scatter (zeroed in L1)
    atomicAdd(&adjt[eidx(eit, t, s64t) * Nn + eidx(eit, Ee + t, s64t)], 1.0f);

    int c = t & 3, e0 = t >> 2;                       // e0 in 0..16383
    int s[4], d[4];
#pragma unroll
    for (int k = 0; k < 4; k++) {
        int e = e0 + k * 16384;
        s[k] = eidx(ei, e, is64);
        d[k] = eidx(ei, Ee + e, is64);
    }
    float nw[4];
#pragma unroll
    for (int k = 0; k < 4; k++)
        nw[k] = rsqrtf((sdeg[s[k]] + 1.0f) * (sdeg[d[k]] + 1.0f));
    const float4* xw4 = (const float4*)g_xw;
    float4 a[4], b[4];
#pragma unroll
    for (int k = 0; k < 4; k++) {
        a[k] = xw4[s[k] * 8 + c];
        b[k] = xw4[s[k] * 8 + c + 4];
    }
#pragma unroll
    for (int k = 0; k < 4; k++) {
        float w = nw[k];
        a[k].x *= w; a[k].y *= w; a[k].z *= w; a[k].w *= w;
        b[k].x *= w; b[k].y *= w; b[k].z *= w; b[k].w *= w;
        red4(&g_agg1[d[k] * HIDc + c * 4], a[k]);
        red4(&g_agg1[d[k] * HIDc + (c + 4) * 4], b[k]);
    }
}

// L3: h1 = relu(agg + selfloop + b1) fused with hw = h1 @ {W_mu, W_lv}; reset agg1
__global__ void k_h1hw(const float* __restrict__ b1,
                       const float* __restrict__ Wmu, const float* __restrict__ Wlv) {
    int row  = blockIdx.x * 8 + (threadIdx.x >> 5);
    int lane = threadIdx.x & 31;
    float di = rsqrtf(g_deg[row] + 1.0f);
    int idx = row * HIDc + lane;
    float h = fmaxf(g_agg1[idx] + di * di * g_xw[idx] + b1[lane], 0.f);
    g_agg1[idx] = 0.f;                                // reset for next replay
    const float* W = (lane < 16) ? Wmu : Wlv;
    int l = lane & 15;
    float s = 0.f;
#pragma unroll
    for (int k = 0; k < HIDc; k++) {
        float hk = __shfl_sync(0xffffffffu, h, k);
        s = fmaf(hk, W[k * LATc + l], s);
    }
    if (lane < 16) g_hwmu[row * LATc + l] = s;
    else           g_hwlv[row * LATc + l] = s;
}

// L4: eagg2 (4 edges/thread, smem deg, fused rsqrt)
__global__ void k_eagg2(const void* __restrict__ ei) {
    __shared__ int   s64;
    __shared__ float sdeg[Nn];
    int tx = threadIdx.x;
    if (tx == 0) s64 = detect64(ei);
    for (int i = tx; i < Nn; i += 256) sdeg[i] = g_deg[i];
    __syncthreads();
    int is64 = s64;
    int t = blockIdx.x * 256 + tx;
    int c = t & 3, e0 = t >> 2;
    int s[4], d[4];
#pragma unroll
    for (int k = 0; k < 4; k++) {
        int e = e0 + k * 16384;
        s[k] = eidx(ei, e, is64);
        d[k] = eidx(ei, Ee + e, is64);
    }
    float nw[4];
#pragma unroll
    for (int k = 0; k < 4; k++)
        nw[k] = rsqrtf((sdeg[s[k]] + 1.0f) * (sdeg[d[k]] + 1.0f));
    float4 a[4], b[4];
#pragma unroll
    for (int k = 0; k < 4; k++) {
        a[k] = ((const float4*)g_hwmu)[s[k] * 4 + c];
        b[k] = ((const float4*)g_hwlv)[s[k] * 4 + c];
    }
#pragma unroll
    for (int k = 0; k < 4; k++) {
        float w = nw[k];
        a[k].x *= w; a[k].y *= w; a[k].z *= w; a[k].w *= w;
        b[k].x *= w; b[k].y *= w; b[k].z *= w; b[k].w *= w;
        red4(&g_aggmu[d[k] * LATc + c * 4], a[k]);
        red4(&g_agglv[d[k] * LATc + c * 4], b[k]);
    }
}

// L5: mu/logvar out, z (regs), hi/hjT via shfl-16 matvec; reset aggmu/agglv/deg
__global__ void k_zhij(const float* __restrict__ bmu, const float* __restrict__ blv,
                       const float* __restrict__ eps,
                       const float* __restrict__ dW1, const float* __restrict__ db1,
                       float* __restrict__ out_mu, float* __restrict__ out_lv) {
    int t = blockIdx.x * 256 + threadIdx.x;           // Nn*LATc threads
    int i = t >> 4, l = t & 15;
    float di = rsqrtf(g_deg[i] + 1.0f);
    float d2 = di * di;
    float mu = g_aggmu[t] + d2 * g_hwmu[t] + bmu[l];
    float lv = g_agglv[t] + d2 * g_hwlv[t] + blv[l];
    g_aggmu[t] = 0.f; g_agglv[t] = 0.f;               // reset for next replay
    if (l == 0) g_deg[i] = 0.f;                       // last deg consumer resets it
    out_mu[t] = mu;
    out_lv[t] = lv;
    float z = fmaf(eps[t], __expf(0.5f * lv), mu);
    float si = db1[l], sj = 0.f;
#pragma unroll
    for (int k = 0; k < LATc; k++) {
        float zk = __shfl_sync(0xffffffffu, z, k, 16);
        si = fmaf(zk, dW1[k * LATc + l], si);
        sj = fmaf(zk, dW1[(LATc + k) * LATc + l], sj);
    }
    g_hi[t] = si;
    g_hjT[l * Nn + i] = sj;                           // transposed for decoder
}

// L6: decoder. scalar math, 2 j/thread, tile 8 rows x 512 cols
__global__ void __launch_bounds__(256) k_dec(const float* __restrict__ dW2,
                                             const float* __restrict__ db2,
                                             float* __restrict__ adj) {
    __shared__ float his[8][16];
    int tx = threadIdx.x;
    int j0 = blockIdx.x * 512;
    int i0 = blockIdx.y * 8;

    if (tx < 128) his[tx >> 4][tx & 15] = g_hi[(i0 + (tx >> 4)) * LATc + (tx & 15)];

    float  w2r[LATc];
    float2 hj [LATc];
#pragma unroll
    for (int l = 0; l < LATc; l++) {
        w2r[l] = dW2[l];
        hj[l]  = *(const float2*)&g_hjT[l * Nn + j0 + 2 * tx];
    }
    float b2 = db2[0];
    __syncthreads();

    size_t obase = (size_t)i0 * Nn + j0 + 2 * tx;
#pragma unroll
    for (int r = 0; r < 8; r++) {
        float ax = b2, ay = b2;
#pragma unroll
        for (int l = 0; l < LATc; l++) {
            float h = his[r][l];
            ax = fmaf(fmaxf(h + hj[l].x, 0.f), w2r[l], ax);
            ay = fmaf(fmaxf(h + hj[l].y, 0.f), w2r[l], ay);
        }
        float2 o;
        o.x = __fdividef(1.f, 1.f + __expf(-ax));
        o.y = __fdividef(1.f, 1.f + __expf(-ay));
        *(float2*)&adj[obase + (size_t)r * Nn] = o;
    }
}

// ---------------- launcher (single stream, 6 nodes) ----------------
extern "C" void kernel_launch(void* const* d_in, const int* in_sizes, int n_in,
                              void* d_out, int out_size) {
    const float* x    = (const float*)d_in[0];
    const float* eps  = (const float*)d_in[1];
    const float* W1   = (const float*)d_in[2];
    const float* b1   = (const float*)d_in[3];
    const float* Wmu  = (const float*)d_in[4];
    const float* bmu  = (const float*)d_in[5];
    const float* Wlv  = (const float*)d_in[6];
    const float* blv  = (const float*)d_in[7];
    const float* dW1  = (const float*)d_in[8];
    const float* db1  = (const float*)d_in[9];
    const float* dW2  = (const float*)d_in[10];
    const float* db2  = (const float*)d_in[11];
    const void*  ei   = d_in[12];
    const void*  eit  = d_in[13];

    float* out      = (float*)d_out;
    float* adj_pred = out;
    float* adj_true = out + (size_t)Nn * Nn;
    float* out_mu   = out + 2 * (size_t)Nn * Nn;
    float* out_lv   = out_mu + Nn * LATc;

    k_pre      <<<256, 256>>>(ei, x, W1, (float4*)adj_true);
    k_eagg1true<<<256, 256>>>(ei, eit, adj_true);
    k_h1hw     <<<256, 256>>>(b1, Wmu, Wlv);
    k_eagg2    <<<256, 256>>>(ei);
    k_zhij     <<<128, 256>>>(bmu, blv, eps, dW1, db1, out_mu, out_lv);
    k_dec      <<<dim3(4, 256), 256>>>(dW2, db2, adj_pred);
}

// round 12
// speedup vs baseline: 1.1581x; 1.0735x over previous
#include <cuda_runtime.h>
#include <cstdint>

#define Nn   2048
#define Ee   65536
#define INC  128
#define HIDc 32
#define LATc 16

typedef unsigned long long ull;

// ---------------- scratch (static zero; self-cleaning each run) ----------------
__device__ float g_deg [Nn];                       // edge count; reset in k_zhij
__device__ __align__(16) float g_xw  [Nn*HIDc];
__device__ __align__(16) float g_agg1[Nn*HIDc];   // reset in k_zhij
__device__ __align__(16) float g_aggh[Nn*HIDc];   // reset in k_zhij
__device__ __align__(16) float g_hi  [Nn*LATc];
__device__ __align__(16) float g_hjT [LATc*Nn];   // transposed: [l][i]

// ---------------- helpers ----------------
__device__ __forceinline__ int eidx(const void* p, int pos, int is64) {
    if (is64) return (int)((const long long*)p)[pos];
    return ((const int*)p)[pos];
}
// per-block dtype detect: ids < 2048 => int64 storage has zero high words
__device__ __forceinline__ int detect64(const void* p_) {
    const ull* p = (const ull*)p_;
    ull orv = 0;
#pragma unroll
    for (int k = 0; k < 64; k++) orv |= p[k];
    return ((orv >> 32) == 0ull) ? 1 : 0;
}
__device__ __forceinline__ void red4(float* addr, float4 v) {
    asm volatile("red.global.add.v4.f32 [%0], {%1, %2, %3, %4};"
                 :: "l"(__cvta_generic_to_global(addr)),
                    "f"(v.x), "f"(v.y), "f"(v.z), "f"(v.w) : "memory");
}

// ---------------- kernels ----------------

// L1: deg atomics | xw = x @ W1 (8 rows/block) | zero adj_true  (all independent)
__global__ void k_pre(const void* __restrict__ ei,
                      const float* __restrict__ x, const float* __restrict__ W1,
                      float4* __restrict__ adjt4) {
    __shared__ float xs[8][INC];
    __shared__ int   s64;
    int tid = threadIdx.x;                            // 256 threads, 256 blocks
    int t   = blockIdx.x * 256 + tid;                 // 0..65535
    if (tid == 0) s64 = detect64(ei);

    // zero adj_true: 16 float4 per thread (coalesced, full 16.8MB)
#pragma unroll
    for (int k = 0; k < 16; k++)
        adjt4[t + k * 65536] = make_float4(0.f, 0.f, 0.f, 0.f);

    // fill x tile for this block's 8 GEMM rows
    for (int u = tid; u < 8 * INC; u += 256) {
        int r = u / INC, k = u % INC;
        xs[r][k] = x[(blockIdx.x * 8 + r) * INC + k];
    }
    __syncthreads();

    // one degree atomic per thread
    atomicAdd(&g_deg[eidx(ei, Ee + t, s64)], 1.0f);

    // warp-per-row GEMM: row = 8*block + warp, c = lane
    int row = blockIdx.x * 8 + (tid >> 5);
    int c   = tid & 31;
    float s = 0.f;
#pragma unroll 8
    for (int k = 0; k < INC; k++) s = fmaf(xs[tid >> 5][k], W1[k * HIDc + c], s);
    g_xw[row * HIDc + c] = s;
}

// L2: eagg1 (8 threads/edge, 1 red4 each) | adj_true scatter (1 thread/edge)
__global__ void k_eagg1true(const void* __restrict__ ei,
                            const void* __restrict__ eit, float* __restrict__ adjt) {
    __shared__ int s64, s64t;
    int tx = threadIdx.x;
    if (tx == 0)  s64  = detect64(ei);
    if (tx == 32) s64t = detect64(eit);
    __syncthreads();
    int t = blockIdx.x * 256 + tx;                    // 524288 threads
    int e = t >> 3, c = t & 7;
    int s = eidx(ei, e, s64), d = eidx(ei, Ee + e, s64);
    if (c == 0)                                       // one lane per edge scatters
        atomicAdd(&adjt[eidx(eit, e, s64t) * Nn + eidx(eit, Ee + e, s64t)], 1.0f);
    float nw = rsqrtf((g_deg[s] + 1.0f) * (g_deg[d] + 1.0f));
    float4 a = ((const float4*)g_xw)[s * 8 + c];
    a.x *= nw; a.y *= nw; a.z *= nw; a.w *= nw;
    red4(&g_agg1[d * HIDc + c * 4], a);
}

// L3: eagg2 with h1 computed inline per edge (GCN linearity: aggregate h, multiply later)
__global__ void k_eagg2(const void* __restrict__ ei, const float* __restrict__ b1) {
    __shared__ int s64;
    if (threadIdx.x == 0) s64 = detect64(ei);
    __syncthreads();
    int t = blockIdx.x * 256 + threadIdx.x;           // 524288 threads
    int e = t >> 3, c = t & 7;
    int s = eidx(ei, e, s64), d = eidx(ei, Ee + e, s64);
    float ds = g_deg[s];
    float nw = rsqrtf((ds + 1.0f) * (g_deg[d] + 1.0f));
    float d2 = 1.0f / (ds + 1.0f);
    float4 a  = ((const float4*)g_agg1)[s * 8 + c];
    float4 xx = ((const float4*)g_xw)[s * 8 + c];
    float4 bb = ((const float4*)b1)[c];
    float4 h;
    h.x = nw * fmaxf(fmaf(d2, xx.x, a.x) + bb.x, 0.f);
    h.y = nw * fmaxf(fmaf(d2, xx.y, a.y) + bb.y, 0.f);
    h.z = nw * fmaxf(fmaf(d2, xx.z, a.z) + bb.z, 0.f);
    h.w = nw * fmaxf(fmaf(d2, xx.w, a.w) + bb.w, 0.f);
    red4(&g_aggh[d * HIDc + c * 4], h);
}

// L4: warp per node — h1(i) inline, v = aggh + d2*h1, shfl matvecs for mu/lv and hi/hj;
//     writes out_mu/out_lv; resets agg1/aggh/deg
__global__ void k_zhij(const float* __restrict__ b1,
                       const float* __restrict__ Wmu, const float* __restrict__ bmu,
                       const float* __restrict__ Wlv, const float* __restrict__ blv,
                       const float* __restrict__ eps,
                       const float* __restrict__ dW1, const float* __restrict__ db1,
                       float* __restrict__ out_mu, float* __restrict__ out_lv) {
    int i    = (blockIdx.x * 256 + threadIdx.x) >> 5; // node, 2048 warps
    int lane = threadIdx.x & 31;
    int l    = lane & 15;

    float deg = g_deg[i];                             // broadcast load
    float d2  = 1.0f / (deg + 1.0f);
    int idx = i * HIDc + lane;
    float aggh = g_aggh[idx];
    float h1 = fmaxf(fmaf(d2, g_xw[idx], g_agg1[idx]) + b1[lane], 0.f);
    g_agg1[idx] = 0.f; g_aggh[idx] = 0.f;             // reset for next replay
    if (lane == 0) g_deg[i] = 0.f;
    float v = fmaf(d2, h1, aggh);                     // (aggh + d2*h1)

    // mu (lanes 0-15) / logvar (lanes 16-31): 32x16 shfl matvec
    const float* W  = (lane < 16) ? Wmu : Wlv;
    float acc = (lane < 16) ? bmu[l] : blv[l];
#pragma unroll
    for (int k = 0; k < HIDc; k++)
        acc = fmaf(__shfl_sync(0xffffffffu, v, k), W[k * LATc + l], acc);
    if (lane < 16) out_mu[i * LATc + l] = acc;
    else           out_lv[i * LATc + l] = acc;

    // z = mu + eps*exp(0.5*lv) in both halves
    float other = __shfl_xor_sync(0xffffffffu, acc, 16);
    float ev = eps[i * LATc + l];
    float z = (lane < 16) ? fmaf(ev, __expf(0.5f * other), acc)
                          : fmaf(ev, __expf(0.5f * acc), other);

    // hi (lanes 0-15) and hj (lanes 16-31): 16x16 shfl matvecs
    const float* DW = (lane < 16) ? dW1 : dW1 + LATc * LATc;
    float si = (lane < 16) ? db1[l] : 0.f;
#pragma unroll
    for (int k = 0; k < LATc; k++)
        si = fmaf(__shfl_sync(0xffffffffu, z, k), DW[k * LATc + l], si);
    if (lane < 16) g_hi[i * LATc + l] = si;
    else           g_hjT[l * Nn + i]  = si;           // transposed for decoder
}

// L5: decoder. scalar math, 2 j/thread, tile 8 rows x 512 cols
__global__ void __launch_bounds__(256) k_dec(const float* __restrict__ dW2,
                                             const float* __restrict__ db2,
                                             float* __restrict__ adj) {
    __shared__ float his[8][16];
    int tx = threadIdx.x;
    int j0 = blockIdx.x * 512;
    int i0 = blockIdx.y * 8;

    if (tx < 128) his[tx >> 4][tx & 15] = g_hi[(i0 + (tx >> 4)) * LATc + (tx & 15)];

    float  w2r[LATc];
    float2 hj [LATc];
#pragma unroll
    for (int l = 0; l < LATc; l++) {
        w2r[l] = dW2[l];
        hj[l]  = *(const float2*)&g_hjT[l * Nn + j0 + 2 * tx];
    }
    float b2 = db2[0];
    __syncthreads();

    size_t obase = (size_t)i0 * Nn + j0 + 2 * tx;
#pragma unroll
    for (int r = 0; r < 8; r++) {
        float ax = b2, ay = b2;
#pragma unroll
        for (int l = 0; l < LATc; l++) {
            float h = his[r][l];
            ax = fmaf(fmaxf(h + hj[l].x, 0.f), w2r[l], ax);
            ay = fmaf(fmaxf(h + hj[l].y, 0.f), w2r[l], ay);
        }
        float2 o;
        o.x = __fdividef(1.f, 1.f + __expf(-ax));
        o.y = __fdividef(1.f, 1.f + __expf(-ay));
        *(float2*)&adj[obase + (size_t)r * Nn] = o;
    }
}

// ---------------- launcher (single stream, 5 nodes) ----------------
extern "C" void kernel_launch(void* const* d_in, const int* in_sizes, int n_in,
                              void* d_out, int out_size) {
    const float* x    = (const float*)d_in[0];
    const float* eps  = (const float*)d_in[1];
    const float* W1   = (const float*)d_in[2];
    const float* b1   = (const float*)d_in[3];
    const float* Wmu  = (const float*)d_in[4];
    const float* bmu  = (const float*)d_in[5];
    const float* Wlv  = (const float*)d_in[6];
    const float* blv  = (const float*)d_in[7];
    const float* dW1  = (const float*)d_in[8];
    const float* db1  = (const float*)d_in[9];
    const float* dW2  = (const float*)d_in[10];
    const float* db2  = (const float*)d_in[11];
    const void*  ei   = d_in[12];
    const void*  eit  = d_in[13];

    float* out      = (float*)d_out;
    float* adj_pred = out;
    float* adj_true = out + (size_t)Nn * Nn;
    float* out_mu   = out + 2 * (size_t)Nn * Nn;
    float* out_lv   = out_mu + Nn * LATc;

    k_pre      <<<256, 256>>>(ei, x, W1, (float4*)adj_true);
    k_eagg1true<<<2048, 256>>>(ei, eit, adj_true);
    k_eagg2    <<<2048, 256>>>(ei, b1);
    k_zhij     <<<256, 256>>>(b1, Wmu, bmu, Wlv, blv, eps, dW1, db1, out_mu, out_lv);
    k_dec      <<<dim3(4, 256), 256>>>(dW2, db2, adj_pred);
}

// round 13
// speedup vs baseline: 1.1934x; 1.0305x over previous
#include <cuda_runtime.h>
#include <cstdint>

#define Nn   2048
#define Ee   65536
#define INC  128
#define HIDc 32
#define LATc 16

typedef unsigned long long ull;

// ---------------- scratch (static zero; self-cleaning each run) ----------------
__device__ float g_deg [Nn];                       // edge count; reset in k_zhij
__device__ __align__(16) float g_xw  [Nn*HIDc];
__device__ __align__(16) float g_agg1[Nn*HIDc];   // reset in k_zhij
__device__ __align__(16) float g_aggh[Nn*HIDc];   // reset in k_zhij
__device__ __align__(16) float g_hi  [Nn*LATc];
__device__ __align__(16) float g_hjT [LATc*Nn];   // transposed: [l][i]

// ---------------- helpers ----------------
__device__ __forceinline__ void pdl_trigger() {    // let successor grid launch
    asm volatile("griddepcontrol.launch_dependents;");
}
__device__ __forceinline__ void pdl_wait() {       // wait: predecessor grid complete+visible
    asm volatile("griddepcontrol.wait;" ::: "memory");
}
__device__ __forceinline__ int eidx(const void* p, int pos, int is64) {
    if (is64) return (int)((const long long*)p)[pos];
    return ((const int*)p)[pos];
}
// per-block dtype detect: ids < 2048 => int64 storage has zero high words
__device__ __forceinline__ int detect64(const void* p_) {
    const ull* p = (const ull*)p_;
    ull orv = 0;
#pragma unroll
    for (int k = 0; k < 64; k++) orv |= p[k];
    return ((orv >> 32) == 0ull) ? 1 : 0;
}
__device__ __forceinline__ void red4(float* addr, float4 v) {
    asm volatile("red.global.add.v4.f32 [%0], {%1, %2, %3, %4};"
                 :: "l"(__cvta_generic_to_global(addr)),
                    "f"(v.x), "f"(v.y), "f"(v.z), "f"(v.w) : "memory");
}

// ---------------- kernels ----------------

// L1: deg atomics | xw = x @ W1 (8 rows/block) | zero adj_true  (all independent)
__global__ void k_pre(const void* __restrict__ ei,
                      const float* __restrict__ x, const float* __restrict__ W1,
                      float4* __restrict__ adjt4) {
    __shared__ float xs[8][INC];
    __shared__ int   s64;
    int tid = threadIdx.x;                            // 256 threads, 256 blocks
    int t   = blockIdx.x * 256 + tid;                 // 0..65535
    if (tid == 0) { pdl_trigger(); s64 = detect64(ei); }

    // zero adj_true: 16 float4 per thread (coalesced, full 16.8MB)
#pragma unroll
    for (int k = 0; k < 16; k++)
        adjt4[t + k * 65536] = make_float4(0.f, 0.f, 0.f, 0.f);

    // fill x tile for this block's 8 GEMM rows
    for (int u = tid; u < 8 * INC; u += 256) {
        int r = u / INC, k = u % INC;
        xs[r][k] = x[(blockIdx.x * 8 + r) * INC + k];
    }
    __syncthreads();

    // one degree atomic per thread
    atomicAdd(&g_deg[eidx(ei, Ee + t, s64)], 1.0f);

    // warp-per-row GEMM: row = 8*block + warp, c = lane
    int row = blockIdx.x * 8 + (tid >> 5);
    int c   = tid & 31;
    float s = 0.f;
#pragma unroll 8
    for (int k = 0; k < INC; k++) s = fmaf(xs[tid >> 5][k], W1[k * HIDc + c], s);
    g_xw[row * HIDc + c] = s;
}

// L2: eagg1 (8 threads/edge, 1 red4 each) | adj_true scatter (1 thread/edge)
__global__ void k_eagg1true(const void* __restrict__ ei,
                            const void* __restrict__ eit, float* __restrict__ adjt) {
    __shared__ int s64, s64t;
    int tx = threadIdx.x;
    if (tx == 0)  { pdl_trigger(); s64 = detect64(ei); }
    if (tx == 32) s64t = detect64(eit);
    __syncthreads();
    // ---- prologue: independent loads (edge indices) overlap predecessor tail ----
    int t = blockIdx.x * 256 + tx;                    // 524288 threads
    int e = t >> 3, c = t & 7;
    int s = eidx(ei, e, s64), d = eidx(ei, Ee + e, s64);
    int ti = eidx(eit, e, s64t), tj = eidx(eit, Ee + e, s64t);
    // ---- dependent part ----
    pdl_wait();
    if (c == 0) atomicAdd(&adjt[ti * Nn + tj], 1.0f); // adjt zeroed by k_pre
    float nw = rsqrtf((g_deg[s] + 1.0f) * (g_deg[d] + 1.0f));
    float4 a = ((const float4*)g_xw)[s * 8 + c];
    a.x *= nw; a.y *= nw; a.z *= nw; a.w *= nw;
    red4(&g_agg1[d * HIDc + c * 4], a);
}

// L3: eagg2 with h1 computed inline per edge (GCN linearity: aggregate h, multiply later)
__global__ void k_eagg2(const void* __restrict__ ei, const float* __restrict__ b1) {
    __shared__ int s64;
    if (threadIdx.x == 0) { pdl_trigger(); s64 = detect64(ei); }
    __syncthreads();
    // ---- prologue: indices + bias (independent of eagg1) ----
    int t = blockIdx.x * 256 + threadIdx.x;           // 524288 threads
    int e = t >> 3, c = t & 7;
    int s = eidx(ei, e, s64), d = eidx(ei, Ee + e, s64);
    float4 bb = ((const float4*)b1)[c];
    // ---- dependent part ----
    pdl_wait();
    float ds = g_deg[s];
    float nw = rsqrtf((ds + 1.0f) * (g_deg[d] + 1.0f));
    float d2 = 1.0f / (ds + 1.0f);
    float4 a  = ((const float4*)g_agg1)[s * 8 + c];
    float4 xx = ((const float4*)g_xw)[s * 8 + c];
    float4 h;
    h.x = nw * fmaxf(fmaf(d2, xx.x, a.x) + bb.x, 0.f);
    h.y = nw * fmaxf(fmaf(d2, xx.y, a.y) + bb.y, 0.f);
    h.z = nw * fmaxf(fmaf(d2, xx.z, a.z) + bb.z, 0.f);
    h.w = nw * fmaxf(fmaf(d2, xx.w, a.w) + bb.w, 0.f);
    red4(&g_aggh[d * HIDc + c * 4], h);
}

// L4: warp per node — h1(i) inline, v = aggh + d2*h1, shfl matvecs for mu/lv and hi/hj;
//     writes out_mu/out_lv; resets agg1/aggh/deg
__global__ void k_zhij(const float* __restrict__ b1,
                       const float* __restrict__ Wmu, const float* __restrict__ bmu,
                       const float* __restrict__ Wlv, const float* __restrict__ blv,
                       const float* __restrict__ eps,
                       const float* __restrict__ dW1, const float* __restrict__ db1,
                       float* __restrict__ out_mu, float* __restrict__ out_lv) {
    if (threadIdx.x == 0) pdl_trigger();
    int i    = (blockIdx.x * 256 + threadIdx.x) >> 5; // node, 2048 warps
    int lane = threadIdx.x & 31;
    int l    = lane & 15;
    // ---- prologue: everything not written by eagg2 ----
    float bias1 = b1[lane];
    float bmlv  = (lane < 16) ? bmu[l] : blv[l];
    float ev    = eps[i * LATc + l];
    float dbv   = (lane < 16) ? db1[l] : 0.f;
    // ---- dependent part ----
    pdl_wait();
    float deg = g_deg[i];                             // broadcast load
    float d2  = 1.0f / (deg + 1.0f);
    int idx = i * HIDc + lane;
    float aggh = g_aggh[idx];
    float h1 = fmaxf(fmaf(d2, g_xw[idx], g_agg1[idx]) + bias1, 0.f);
    g_agg1[idx] = 0.f; g_aggh[idx] = 0.f;             // reset for next replay
    if (lane == 0) g_deg[i] = 0.f;
    float v = fmaf(d2, h1, aggh);                     // (aggh + d2*h1)

    // mu (lanes 0-15) / logvar (lanes 16-31): 32x16 shfl matvec
    const float* W  = (lane < 16) ? Wmu : Wlv;
    float acc = bmlv;
#pragma unroll
    for (int k = 0; k < HIDc; k++)
        acc = fmaf(__shfl_sync(0xffffffffu, v, k), W[k * LATc + l], acc);
    if (lane < 16) out_mu[i * LATc + l] = acc;
    else           out_lv[i * LATc + l] = acc;

    // z = mu + eps*exp(0.5*lv) in both halves
    float other = __shfl_xor_sync(0xffffffffu, acc, 16);
    float z = (lane < 16) ? fmaf(ev, __expf(0.5f * other), acc)
                          : fmaf(ev, __expf(0.5f * acc), other);

    // hi (lanes 0-15) and hj (lanes 16-31): 16x16 shfl matvecs
    const float* DW = (lane < 16) ? dW1 : dW1 + LATc * LATc;
    float si = dbv;
#pragma unroll
    for (int k = 0; k < LATc; k++)
        si = fmaf(__shfl_sync(0xffffffffu, z, k), DW[k * LATc + l], si);
    if (lane < 16) g_hi[i * LATc + l] = si;
    else           g_hjT[l * Nn + i]  = si;           // transposed for decoder
}

// L5: decoder. scalar math, 2 j/thread, tile 8 rows x 512 cols
__global__ void __launch_bounds__(256) k_dec(const float* __restrict__ dW2,
                                             const float* __restrict__ db2,
                                             float* __restrict__ adj) {
    __shared__ float his[8][16];
    int tx = threadIdx.x;
    int j0 = blockIdx.x * 512;
    int i0 = blockIdx.y * 8;
    // ---- prologue: weights/bias (independent of zhij) ----
    float w2r[LATc];
#pragma unroll
    for (int l = 0; l < LATc; l++) w2r[l] = dW2[l];
    float b2 = db2[0];
    // ---- dependent part ----
    pdl_wait();
    if (tx < 128) his[tx >> 4][tx & 15] = g_hi[(i0 + (tx >> 4)) * LATc + (tx & 15)];
    float2 hj[LATc];
#pragma unroll
    for (int l = 0; l < LATc; l++)
        hj[l] = *(const float2*)&g_hjT[l * Nn + j0 + 2 * tx];
    __syncthreads();

    size_t obase = (size_t)i0 * Nn + j0 + 2 * tx;
#pragma unroll
    for (int r = 0; r < 8; r++) {
        float ax = b2, ay = b2;
#pragma unroll
        for (int l = 0; l < LATc; l++) {
            float h = his[r][l];
            ax = fmaf(fmaxf(h + hj[l].x, 0.f), w2r[l], ax);
            ay = fmaf(fmaxf(h + hj[l].y, 0.f), w2r[l], ay);
        }
        float2 o;
        o.x = __fdividef(1.f, 1.f + __expf(-ax));
        o.y = __fdividef(1.f, 1.f + __expf(-ay));
        *(float2*)&adj[obase + (size_t)r * Nn] = o;
    }
}

// ---------------- launcher: 5 nodes chained with PDL ----------------
template <typename... Args>
static void launch_pdl(void (*kern)(Args...), dim3 grid, dim3 block, Args... args) {
    cudaLaunchConfig_t cfg = {};
    cfg.gridDim = grid; cfg.blockDim = block; cfg.stream = 0;
    cudaLaunchAttribute at[1];
    at[0].id = cudaLaunchAttributeProgrammaticStreamSerialization;
    at[0].val.programmaticStreamSerializationAllowed = 1;
    cfg.attrs = at; cfg.numAttrs = 1;
    if (cudaLaunchKernelEx(&cfg, kern, args...) != cudaSuccess) {
        // fallback: plain serialized launch (pdl_wait degrades to no-op)
        void* pargs[] = { (void*)&args... };
        cudaLaunchKernel((const void*)kern, grid, block, pargs, 0, 0);
    }
}

extern "C" void kernel_launch(void* const* d_in, const int* in_sizes, int n_in,
                              void* d_out, int out_size) {
    const float* x    = (const float*)d_in[0];
    const float* eps  = (const float*)d_in[1];
    const float* W1   = (const float*)d_in[2];
    const float* b1   = (const float*)d_in[3];
    const float* Wmu  = (const float*)d_in[4];
    const float* bmu  = (const float*)d_in[5];
    const float* Wlv  = (const float*)d_in[6];
    const float* blv  = (const float*)d_in[7];
    const float* dW1  = (const float*)d_in[8];
    const float* db1  = (const float*)d_in[9];
    const float* dW2  = (const float*)d_in[10];
    const float* db2  = (const float*)d_in[11];
    const void*  ei   = d_in[12];
    const void*  eit  = d_in[13];

    float* out      = (float*)d_out;
    float* adj_pred = out;
    float* adj_true = out + (size_t)Nn * Nn;
    float* out_mu   = out + 2 * (size_t)Nn * Nn;
    float* out_lv   = out_mu + Nn * LATc;

    launch_pdl(k_pre,       dim3(256), dim3(256), ei, x, W1, (float4*)adj_true);
    launch_pdl(k_eagg1true, dim3(2048), dim3(256), ei, eit, adj_true);
    launch_pdl(k_eagg2,     dim3(2048), dim3(256), ei, b1);
    launch_pdl(k_zhij,      dim3(256), dim3(256), b1, Wmu, bmu, Wlv, blv, eps, dW1, db1, out_mu, out_lv);
    launch_pdl(k_dec,       dim3(4, 256), dim3(256), dW2, db2, adj_pred);
}